// round 3
// baseline (speedup 1.0000x reference)
#include <cuda_runtime.h>
#include <cstdint>

// ---------------------------------------------------------------------------
// FMForecaster: 16-step flow ODE over a 3-layer MLP, fully fused.
// rows = (b, s) pairs, 12800 total; each block owns 32 rows for all 16 steps.
// GEMM1 reduced to K=24 via precomputed ctx contribution (base[b][h]).
// Inner loops use packed fma.rn.f32x2 (Blackwell 2x FP32).
// ---------------------------------------------------------------------------

namespace {
constexpr int B_    = 128;
constexpr int S_    = 100;
constexpr int PRED  = 24;
constexpr int CTXN  = 96;
constexpr int HID   = 256;
constexpr int STEPS = 16;
constexpr int ROWS  = 32;    // rows per block
constexpr int LDA   = 264;   // padded row stride for activation buffers
constexpr int LDW3  = 260;   // padded stride for transposed W3
constexpr float DT  = 0.0625f;  // 1/16
}

__device__ float g_loc[B_];
__device__ float g_base[B_ * HID];

__device__ __forceinline__ unsigned long long pack2(float a) {
    unsigned long long r;
    asm("mov.b64 %0, {%1, %1};" : "=l"(r) : "f"(a));
    return r;
}
__device__ __forceinline__ void fma2(unsigned long long& d,
                                     unsigned long long a,
                                     unsigned long long b) {
    asm("fma.rn.f32x2 %0, %1, %2, %0;" : "+l"(d) : "l"(a), "l"(b));
}
__device__ __forceinline__ float2 unpack2(unsigned long long v) {
    float lo, hi;
    asm("mov.b64 {%0, %1}, %2;" : "=f"(lo), "=f"(hi) : "l"(v));
    return make_float2(lo, hi);
}

// ---------------------------------------------------------------------------
// Precompute: loc[b] and base[b][h] = b1[h] + sum_j (ctx[b][j]/loc[b]) * W1[26+j][h]
// grid = 128 blocks (one per b), 256 threads (one per h)
// ---------------------------------------------------------------------------
__global__ void precompute_kernel(const float* __restrict__ past_target,
                                  const float* __restrict__ W1,
                                  const float* __restrict__ b1) {
    __shared__ float s_scaled[CTXN];
    __shared__ float s_loc;
    const int b = blockIdx.x;
    const int t = threadIdx.x;
    const float* ctx = past_target + b * CTXN;  // L == CTX == 96

    if (t == 0) {
        float s = 0.f;
        for (int j = 0; j < CTXN; j++) s += fabsf(ctx[j]);
        float loc = s * (1.0f / CTXN);
        loc = fmaxf(loc, 1e-6f);
        s_loc = loc;
        g_loc[b] = loc;
    }
    __syncthreads();
    const float inv = 1.0f / s_loc;
    if (t < CTXN) s_scaled[t] = ctx[t] * inv;
    __syncthreads();

    float acc = b1[t];
    const float* Wc = W1 + 26 * HID + t;
#pragma unroll 8
    for (int j = 0; j < CTXN; j++) acc = fmaf(s_scaled[j], Wc[j * HID], acc);
    g_base[b * HID + t] = acc;
}

// ---------------------------------------------------------------------------
// Main fused kernel
// ---------------------------------------------------------------------------
extern __shared__ float smem[];

__global__ void __launch_bounds__(256, 2)
flow_kernel(const float* __restrict__ z0,
            const float* __restrict__ W1,
            const float* __restrict__ W2,
            const float* __restrict__ b2,
            const float* __restrict__ W3,
            const float* __restrict__ b3,
            float* __restrict__ out) {
    float* sA     = smem;                    // [ROWS][LDA]  h1
    float* sB     = sA + ROWS * LDA;         // [ROWS][LDA]  h2
    float* sW     = sB + ROWS * LDA;         // [8][HID]     weight chunk
    float* sW3t   = sW + 8 * HID;            // [PRED][LDW3] W3 transposed
    float* sZ     = sW3t + PRED * LDW3;      // [ROWS][PRED] z state
    float* sR24   = sZ + ROWS * PRED;        // [HID]  W1 row 24 (t feature)
    float* sBias2 = sR24 + HID;              // [HID]
    float* sB3    = sBias2 + HID;            // [32]
    float* sLoc   = sB3 + 32;                // [32]

    const int t    = threadIdx.x;
    const int row0 = blockIdx.x * ROWS;
    const int tr   = t >> 5;      // 0..7
    const int tc   = t & 31;      // 0..31
    const int r0   = tr * 4;      // 4 rows / thread
    const int c0   = tc * 8;      // 8 cols / thread
    const int rg   = t >> 3;      // gemm3: row 0..31
    const int pg   = t & 7;       // gemm3: col group (3 cols)

    // ---- stage step-invariant data ----
    sR24[t]   = W1[24 * HID + t];
    sBias2[t] = b2[t];
    if (t < PRED) sB3[t] = b3[t];
    if (t < ROWS) sLoc[t] = g_loc[(row0 + t) / S_];

    for (int idx = t; idx < HID * PRED; idx += 256) {
        int k = idx / PRED;
        int p = idx - k * PRED;
        sW3t[p * LDW3 + k] = W3[idx];
    }
    {
        int row = row0 + rg;
        int b = row / S_, s = row - b * S_;
        const float* zs = z0 + (s * B_ + b) * PRED + pg * 3;
        sZ[rg * PRED + pg * 3 + 0] = zs[0];
        sZ[rg * PRED + pg * 3 + 1] = zs[1];
        sZ[rg * PRED + pg * 3 + 2] = zs[2];
    }
    __syncthreads();

    float r24[8], bi2[8];
#pragma unroll
    for (int j = 0; j < 8; j++) { r24[j] = sR24[c0 + j]; bi2[j] = sBias2[c0 + j]; }
    int rb[4];
#pragma unroll
    for (int i = 0; i < 4; i++) rb[i] = (row0 + r0 + i) / S_;

    for (int step = 0; step < STEPS; step++) {
        const float tk = 1.0f - step * DT;

        // ================= GEMM1: sZ(32x24) @ W1[0:24] -> sA =================
        {
            unsigned long long acc[4][4];
#pragma unroll
            for (int i = 0; i < 4; i++)
#pragma unroll
                for (int j = 0; j < 4; j++) acc[i][j] = 0ull;

            const float4* wsrc = reinterpret_cast<const float4*>(W1);
            float4 pf0 = wsrc[t];
            float4 pf1 = wsrc[256 + t];
#pragma unroll
            for (int ch = 0; ch < 3; ch++) {
                __syncthreads();
                reinterpret_cast<float4*>(sW)[t]       = pf0;
                reinterpret_cast<float4*>(sW)[256 + t] = pf1;
                __syncthreads();
                if (ch < 2) {
                    pf0 = wsrc[(ch + 1) * 512 + t];
                    pf1 = wsrc[(ch + 1) * 512 + 256 + t];
                }
#pragma unroll
                for (int kk = 0; kk < 8; kk++) {
                    const int k = ch * 8 + kk;
                    unsigned long long a2[4];
#pragma unroll
                    for (int i = 0; i < 4; i++) a2[i] = pack2(sZ[(r0 + i) * PRED + k]);
                    const unsigned long long* w =
                        reinterpret_cast<const unsigned long long*>(sW + kk * HID + c0);
                    unsigned long long w0 = w[0], w1 = w[1], w2 = w[2], w3 = w[3];
#pragma unroll
                    for (int i = 0; i < 4; i++) {
                        fma2(acc[i][0], a2[i], w0);
                        fma2(acc[i][1], a2[i], w1);
                        fma2(acc[i][2], a2[i], w2);
                        fma2(acc[i][3], a2[i], w3);
                    }
                }
            }
            // epilogue: + tk*W1row24 + base[b]; relu
#pragma unroll
            for (int i = 0; i < 4; i++) {
                const float* gb = g_base + rb[i] * HID + c0;
                float4 gb0 = *reinterpret_cast<const float4*>(gb);
                float4 gb1 = *reinterpret_cast<const float4*>(gb + 4);
                float bb[8] = {gb0.x, gb0.y, gb0.z, gb0.w, gb1.x, gb1.y, gb1.z, gb1.w};
                float o[8];
#pragma unroll
                for (int j = 0; j < 4; j++) {
                    float2 v = unpack2(acc[i][j]);
                    o[2 * j + 0] = fmaxf(fmaf(tk, r24[2 * j + 0], v.x + bb[2 * j + 0]), 0.f);
                    o[2 * j + 1] = fmaxf(fmaf(tk, r24[2 * j + 1], v.y + bb[2 * j + 1]), 0.f);
                }
                float* dst = sA + (r0 + i) * LDA + c0;
                *reinterpret_cast<float4*>(dst)     = make_float4(o[0], o[1], o[2], o[3]);
                *reinterpret_cast<float4*>(dst + 4) = make_float4(o[4], o[5], o[6], o[7]);
            }
        }
        __syncthreads();

        // ================= GEMM2: sA(32x256) @ W2 -> sB =================
        {
            unsigned long long acc[4][4];
#pragma unroll
            for (int i = 0; i < 4; i++)
#pragma unroll
                for (int j = 0; j < 4; j++) acc[i][j] = 0ull;

            const float4* wsrc = reinterpret_cast<const float4*>(W2);
            float4 pf0 = wsrc[t];
            float4 pf1 = wsrc[256 + t];
            for (int ch = 0; ch < 32; ch++) {
                __syncthreads();
                reinterpret_cast<float4*>(sW)[t]       = pf0;
                reinterpret_cast<float4*>(sW)[256 + t] = pf1;
                __syncthreads();
                if (ch < 31) {
                    pf0 = wsrc[(ch + 1) * 512 + t];
                    pf1 = wsrc[(ch + 1) * 512 + 256 + t];
                }
                const int kb = ch * 8;
#pragma unroll
                for (int kk = 0; kk < 8; kk++) {
                    unsigned long long a2[4];
#pragma unroll
                    for (int i = 0; i < 4; i++) a2[i] = pack2(sA[(r0 + i) * LDA + kb + kk]);
                    const unsigned long long* w =
                        reinterpret_cast<const unsigned long long*>(sW + kk * HID + c0);
                    unsigned long long w0 = w[0], w1 = w[1], w2 = w[2], w3 = w[3];
#pragma unroll
                    for (int i = 0; i < 4; i++) {
                        fma2(acc[i][0], a2[i], w0);
                        fma2(acc[i][1], a2[i], w1);
                        fma2(acc[i][2], a2[i], w2);
                        fma2(acc[i][3], a2[i], w3);
                    }
                }
            }
            // epilogue: relu(+b2)
#pragma unroll
            for (int i = 0; i < 4; i++) {
                float o[8];
#pragma unroll
                for (int j = 0; j < 4; j++) {
                    float2 v = unpack2(acc[i][j]);
                    o[2 * j + 0] = fmaxf(v.x + bi2[2 * j + 0], 0.f);
                    o[2 * j + 1] = fmaxf(v.y + bi2[2 * j + 1], 0.f);
                }
                float* dst = sB + (r0 + i) * LDA + c0;
                *reinterpret_cast<float4*>(dst)     = make_float4(o[0], o[1], o[2], o[3]);
                *reinterpret_cast<float4*>(dst + 4) = make_float4(o[4], o[5], o[6], o[7]);
            }
        }
        __syncthreads();

        // ================= GEMM3: sB(32x256) @ W3 -> v; z -= dt*v =================
        {
            const float* bp  = sB + rg * LDA;
            const float* w0p = sW3t + (pg * 3 + 0) * LDW3;
            const float* w1p = sW3t + (pg * 3 + 1) * LDW3;
            const float* w2p = sW3t + (pg * 3 + 2) * LDW3;
            float a0 = 0.f, a1 = 0.f, a2s = 0.f;
#pragma unroll 8
            for (int k = 0; k < HID; k += 4) {
                float4 a  = *reinterpret_cast<const float4*>(bp + k);
                float4 w0 = *reinterpret_cast<const float4*>(w0p + k);
                float4 w1 = *reinterpret_cast<const float4*>(w1p + k);
                float4 w2 = *reinterpret_cast<const float4*>(w2p + k);
                a0  = fmaf(a.x, w0.x, fmaf(a.y, w0.y, fmaf(a.z, w0.z, fmaf(a.w, w0.w, a0))));
                a1  = fmaf(a.x, w1.x, fmaf(a.y, w1.y, fmaf(a.z, w1.z, fmaf(a.w, w1.w, a1))));
                a2s = fmaf(a.x, w2.x, fmaf(a.y, w2.y, fmaf(a.z, w2.z, fmaf(a.w, w2.w, a2s))));
            }
            const int zi = rg * PRED + pg * 3;
            sZ[zi + 0] -= DT * (a0  + sB3[pg * 3 + 0]);
            sZ[zi + 1] -= DT * (a1  + sB3[pg * 3 + 1]);
            sZ[zi + 2] -= DT * (a2s + sB3[pg * 3 + 2]);
        }
        __syncthreads();
    }

    // ---- output: out[b][s][p] = zT * loc[b] ----
    {
        const int row = row0 + rg;
        const float loc = sLoc[rg];
        float* o = out + row * PRED + pg * 3;   // row = b*S_+s  ->  b*2400 + s*24
        const int zi = rg * PRED + pg * 3;
        o[0] = sZ[zi + 0] * loc;
        o[1] = sZ[zi + 1] * loc;
        o[2] = sZ[zi + 2] * loc;
    }
}

// ---------------------------------------------------------------------------
extern "C" void kernel_launch(void* const* d_in, const int* in_sizes, int n_in,
                              void* d_out, int out_size) {
    (void)in_sizes; (void)n_in; (void)out_size;
    const float* past_target = (const float*)d_in[0];
    // d_in[1] = past_observed_values (unused by reference math)
    const float* z0 = (const float*)d_in[2];
    const float* W1 = (const float*)d_in[3];
    const float* b1 = (const float*)d_in[4];
    const float* W2 = (const float*)d_in[5];
    const float* b2 = (const float*)d_in[6];
    const float* W3 = (const float*)d_in[7];
    const float* b3 = (const float*)d_in[8];
    float* out = (float*)d_out;

    const size_t smem_floats = (size_t)ROWS * LDA * 2 + 8 * HID + PRED * LDW3 +
                               ROWS * PRED + HID + HID + 32 + 32;
    const size_t smem_bytes = smem_floats * sizeof(float);
    cudaFuncSetAttribute(flow_kernel, cudaFuncAttributeMaxDynamicSharedMemorySize,
                         (int)smem_bytes);

    precompute_kernel<<<B_, HID>>>(past_target, W1, b1);
    flow_kernel<<<(S_ * B_) / ROWS, 256, smem_bytes>>>(z0, W1, W2, b2, W3, b3, out);
}

// round 4
// speedup vs baseline: 1.1961x; 1.1961x over previous
#include <cuda_runtime.h>
#include <cstdint>

typedef unsigned long long u64;

// ---------------------------------------------------------------------------
// FMForecaster: 16-step flow ODE over 3-layer MLP, fully fused, fp32x2 SIMT.
// 256 blocks x 50 rows, 160 threads (5 warps x 10 rows), thread tile 10x8.
// Single shared activation buffer; W1/W2 streamed from L2 via reg-prefetch.
// GEMM1 reduced to K=25 (z 0..23 + t as row 24); ctx+b1 via g_base.
// ---------------------------------------------------------------------------

namespace {
constexpr int B_    = 128;
constexpr int S_    = 100;
constexpr int PRED  = 24;
constexpr int CTXN  = 96;
constexpr int HID   = 256;
constexpr int STEPS = 16;
constexpr int ROWS  = 50;      // rows per block -> 256 blocks (single wave @occ2)
constexpr int THREADS = 160;   // 5 warps
constexpr int RPW   = 10;      // rows per warp / per thread
constexpr int LDA   = 260;     // activation row stride (row-major)
constexpr int LDZ   = 52;      // z k-major row stride
constexpr int LDW3  = 260;     // W3t row stride
constexpr float DT  = 0.0625f;
}

__device__ float g_loc[B_];
__device__ float g_base[B_ * HID];

__device__ __forceinline__ u64 pack2(float a) {
    u64 r; asm("mov.b64 %0, {%1, %1};" : "=l"(r) : "f"(a)); return r;
}
__device__ __forceinline__ u64 packpair(float a, float b) {
    u64 r; asm("mov.b64 %0, {%1, %2};" : "=l"(r) : "f"(a), "f"(b)); return r;
}
__device__ __forceinline__ void fma2(u64& d, u64 a, u64 b) {
    asm("fma.rn.f32x2 %0, %1, %2, %0;" : "+l"(d) : "l"(a), "l"(b));
}
__device__ __forceinline__ float2 unpack2(u64 v) {
    float lo, hi; asm("mov.b64 {%0, %1}, %2;" : "=f"(lo), "=f"(hi) : "l"(v));
    return make_float2(lo, hi);
}

// ---------------------------------------------------------------------------
// Precompute: loc[b]; base[b][h] = b1[h] + sum_j (ctx[b][j]/loc[b])*W1[26+j][h]
// ---------------------------------------------------------------------------
__global__ void precompute_kernel(const float* __restrict__ past_target,
                                  const float* __restrict__ W1,
                                  const float* __restrict__ b1) {
    __shared__ float s_scaled[CTXN];
    __shared__ float s_loc;
    const int b = blockIdx.x;
    const int t = threadIdx.x;
    const float* ctx = past_target + b * CTXN;   // L == CTX == 96

    if (t == 0) {
        float s = 0.f;
        for (int j = 0; j < CTXN; j++) s += fabsf(ctx[j]);
        float loc = fmaxf(s * (1.0f / CTXN), 1e-6f);
        s_loc = loc;
        g_loc[b] = loc;
    }
    __syncthreads();
    const float inv = 1.0f / s_loc;
    if (t < CTXN) s_scaled[t] = ctx[t] * inv;
    __syncthreads();

    float acc = b1[t];
    const float* Wc = W1 + 26 * HID + t;
#pragma unroll 8
    for (int j = 0; j < CTXN; j++) acc = fmaf(s_scaled[j], Wc[j * HID], acc);
    g_base[b * HID + t] = acc;
}

// ---------------------------------------------------------------------------
// mma chunk helpers: acc[i][j] += a(row i, k) * w(k, c0+2j..2j+1) over KLEN ks
// ---------------------------------------------------------------------------
template <int KLEN>
__device__ __forceinline__ void mma_chunk_rowmajor(u64 acc[RPW][4],
                                                   const float* __restrict__ aBase,  // sAct + r0*LDA + kb
                                                   const float* __restrict__ sW,
                                                   int c0) {
#pragma unroll
    for (int kk = 0; kk < KLEN; kk++) {
        const u64* wr = reinterpret_cast<const u64*>(sW + kk * HID + c0);
        u64 w0 = wr[0], w1 = wr[1], w2 = wr[2], w3 = wr[3];
#pragma unroll
        for (int i = 0; i < RPW; i++) {
            u64 a = pack2(aBase[i * LDA + kk]);
            fma2(acc[i][0], a, w0);
            fma2(acc[i][1], a, w1);
            fma2(acc[i][2], a, w2);
            fma2(acc[i][3], a, w3);
        }
    }
}

template <int KLEN>
__device__ __forceinline__ void mma_chunk_kmajor(u64 acc[RPW][4],
                                                 const float* __restrict__ aBase,  // sZt + kb*LDZ + r0
                                                 const float* __restrict__ sW,
                                                 int c0) {
#pragma unroll
    for (int kk = 0; kk < KLEN; kk++) {
        const u64* wr = reinterpret_cast<const u64*>(sW + kk * HID + c0);
        u64 w0 = wr[0], w1 = wr[1], w2 = wr[2], w3 = wr[3];
        const float* ar = aBase + kk * LDZ;
#pragma unroll
        for (int i = 0; i < RPW; i++) {
            u64 a = pack2(ar[i]);
            fma2(acc[i][0], a, w0);
            fma2(acc[i][1], a, w1);
            fma2(acc[i][2], a, w2);
            fma2(acc[i][3], a, w3);
        }
    }
}

// ---------------------------------------------------------------------------
// Main fused kernel
// ---------------------------------------------------------------------------
extern __shared__ float smem[];

__global__ void __launch_bounds__(THREADS, 2)
flow_kernel(const float* __restrict__ z0,
            const float* __restrict__ W1,
            const float* __restrict__ W2,
            const float* __restrict__ b2,
            const float* __restrict__ W3,
            const float* __restrict__ b3,
            float* __restrict__ out) {
    float* sAct  = smem;                   // [50][260]  h1 then h2 (reused)
    float* sW    = sAct + ROWS * LDA;      // [16][256]  streamed weight chunk
    float* sW3t  = sW + 16 * HID;          // [24][260]  W3 transposed
    float* sZt   = sW3t + PRED * LDW3;     // [25][52]   z k-major (+ t row 24)
    float* sBase = sZt + 25 * LDZ;         // [2][256]   g_base for block's b's
    float* sB3   = sBase + 2 * HID;        // [24]
    float* sLoc  = sB3 + PRED;             // [50]

    const int tid  = threadIdx.x;
    const int warp = tid >> 5;             // 0..4
    const int lane = tid & 31;
    const int r0   = warp * RPW;           // first row of this warp
    const int c0   = lane * 8;             // first col of this thread
    const int row0 = blockIdx.x * ROWS;
    const int b0   = row0 / S_;

    const float4* W1f4 = reinterpret_cast<const float4*>(W1);
    const float4* W2f4 = reinterpret_cast<const float4*>(W2);
    float4* sWf4 = reinterpret_cast<float4*>(sW);

    // ---- one-time staging ----
    for (int idx = tid; idx < HID * PRED; idx += THREADS) {
        int k = idx / PRED, p = idx - k * PRED;
        sW3t[p * LDW3 + k] = W3[idx];
    }
    for (int c = tid; c < 2 * HID; c += THREADS) {
        int bsel = c >> 8, cc = c & 255;
        int bb = min(b0 + bsel, B_ - 1);
        sBase[c] = g_base[bb * HID + cc];
    }
    if (tid < PRED) sB3[tid] = b3[tid];
    if (tid < ROWS) sLoc[tid] = g_loc[(row0 + tid) / S_];
    for (int idx = tid; idx < ROWS * PRED; idx += THREADS) {
        int r = idx / PRED, p = idx - r * PRED;
        int row = row0 + r, b = row / S_, s = row - b * S_;
        sZt[p * LDZ + r] = z0[(s * B_ + b) * PRED + p];
    }

    float bi2[8];
    {
        float4 v0 = reinterpret_cast<const float4*>(b2)[lane * 2];
        float4 v1 = reinterpret_cast<const float4*>(b2)[lane * 2 + 1];
        bi2[0] = v0.x; bi2[1] = v0.y; bi2[2] = v0.z; bi2[3] = v0.w;
        bi2[4] = v1.x; bi2[5] = v1.y; bi2[6] = v1.z; bi2[7] = v1.w;
    }
    int bsel_r[RPW];
#pragma unroll
    for (int i = 0; i < RPW; i++) bsel_r[i] = (row0 + r0 + i) / S_ - b0;

    __syncthreads();

    for (int step = 0; step < STEPS; step++) {
        const float tk = 1.0f - step * DT;
        // t-feature: row 24 of k-major z buffer (own-thread write; ordered by
        // the barrier at the top of GEMM1 chunk 0 staging)
        if (tid < ROWS) sZt[24 * LDZ + tid] = tk;

        // ============== GEMM1: x(50x25) @ W1[0:25] -> h1 (sAct) ==============
        u64 acc[RPW][4];
#pragma unroll
        for (int i = 0; i < RPW; i++)
#pragma unroll
            for (int j = 0; j < 4; j++) acc[i][j] = 0ull;

        __syncthreads();
        for (int idx = tid; idx < 1024; idx += THREADS) sWf4[idx] = W1f4[idx];
        __syncthreads();
        mma_chunk_kmajor<16>(acc, sZt + r0, sW, c0);

        __syncthreads();
        for (int idx = tid; idx < 576; idx += THREADS) sWf4[idx] = W1f4[1024 + idx];
        __syncthreads();
        mma_chunk_kmajor<9>(acc, sZt + 16 * LDZ + r0, sW, c0);

        // epilogue: relu(acc + base[b][c]) -> sAct row-major
        // (any barrier above also ordered prev-step GEMM3 reads of sAct)
#pragma unroll
        for (int i = 0; i < RPW; i++) {
            const float* bp = sBase + bsel_r[i] * HID + c0;
            float o[8];
#pragma unroll
            for (int j = 0; j < 4; j++) {
                float2 v = unpack2(acc[i][j]);
                o[2 * j + 0] = fmaxf(v.x + bp[2 * j + 0], 0.f);
                o[2 * j + 1] = fmaxf(v.y + bp[2 * j + 1], 0.f);
            }
            float* dst = sAct + (r0 + i) * LDA + c0;
            *reinterpret_cast<float4*>(dst)     = make_float4(o[0], o[1], o[2], o[3]);
            *reinterpret_cast<float4*>(dst + 4) = make_float4(o[4], o[5], o[6], o[7]);
        }

        // ============== GEMM2: h1(50x256) @ W2 -> h2 (sAct, reused) ==============
#pragma unroll
        for (int i = 0; i < RPW; i++)
#pragma unroll
            for (int j = 0; j < 4; j++) acc[i][j] = 0ull;

        float4 pf[7];
        {
            const float4* src = W2f4;
#pragma unroll
            for (int j = 0; j < 7; j++) {
                int idx = tid + j * THREADS;
                if (idx < 1024) pf[j] = src[idx];
            }
        }
        for (int ch = 0; ch < 16; ch++) {
            __syncthreads();   // consumers done with sW (and ch0: h1 visible)
#pragma unroll
            for (int j = 0; j < 7; j++) {
                int idx = tid + j * THREADS;
                if (idx < 1024) sWf4[idx] = pf[j];
            }
            __syncthreads();
            if (ch < 15) {
                const float4* src = W2f4 + (ch + 1) * 1024;
#pragma unroll
                for (int j = 0; j < 7; j++) {
                    int idx = tid + j * THREADS;
                    if (idx < 1024) pf[j] = src[idx];
                }
            }
            mma_chunk_rowmajor<16>(acc, sAct + r0 * LDA + ch * 16, sW, c0);
        }
        __syncthreads();       // all h1 reads complete before overwrite

        // epilogue: relu(acc + b2) -> sAct (h2)
#pragma unroll
        for (int i = 0; i < RPW; i++) {
            float o[8];
#pragma unroll
            for (int j = 0; j < 4; j++) {
                float2 v = unpack2(acc[i][j]);
                o[2 * j + 0] = fmaxf(v.x + bi2[2 * j + 0], 0.f);
                o[2 * j + 1] = fmaxf(v.y + bi2[2 * j + 1], 0.f);
            }
            float* dst = sAct + (r0 + i) * LDA + c0;
            *reinterpret_cast<float4*>(dst)     = make_float4(o[0], o[1], o[2], o[3]);
            *reinterpret_cast<float4*>(dst + 4) = make_float4(o[4], o[5], o[6], o[7]);
        }
        __syncthreads();       // h2 visible

        // ============== GEMM3: h2(50x256) @ W3 -> v; z -= dt*(v+b3) ==============
        if (tid < 150) {
            const int r  = tid % ROWS;
            const int p0 = (tid / ROWS) * 8;
            const float* arow = sAct + r * LDA;
            u64 acc3[8];
#pragma unroll
            for (int j = 0; j < 8; j++) acc3[j] = 0ull;
#pragma unroll 2
            for (int k = 0; k < HID; k += 4) {
                float4 a4 = *reinterpret_cast<const float4*>(arow + k);
                u64 aLo = packpair(a4.x, a4.y);
                u64 aHi = packpair(a4.z, a4.w);
#pragma unroll
                for (int j = 0; j < 8; j++) {
                    float4 w4 = *reinterpret_cast<const float4*>(sW3t + (p0 + j) * LDW3 + k);
                    fma2(acc3[j], aLo, packpair(w4.x, w4.y));
                    fma2(acc3[j], aHi, packpair(w4.z, w4.w));
                }
            }
#pragma unroll
            for (int j = 0; j < 8; j++) {
                float2 v = unpack2(acc3[j]);
                float vv = v.x + v.y + sB3[p0 + j];
                sZt[(p0 + j) * LDZ + r] -= DT * vv;
            }
        }
        // no trailing barrier needed: next-step GEMM1 staging barrier orders sZt
    }

    // ---- output: out[b][s][p] = zT * loc[b]  (same thread that updated z) ----
    if (tid < 150) {
        const int r  = tid % ROWS;
        const int p0 = (tid / ROWS) * 8;
        const float loc = sLoc[r];
        float* o = out + (row0 + r) * PRED + p0;
#pragma unroll
        for (int j = 0; j < 8; j++) o[j] = sZt[(p0 + j) * LDZ + r] * loc;
    }
}

// ---------------------------------------------------------------------------
extern "C" void kernel_launch(void* const* d_in, const int* in_sizes, int n_in,
                              void* d_out, int out_size) {
    (void)in_sizes; (void)n_in; (void)out_size;
    const float* past_target = (const float*)d_in[0];
    // d_in[1] = past_observed_values (all-ones; unused by reference math)
    const float* z0 = (const float*)d_in[2];
    const float* W1 = (const float*)d_in[3];
    const float* b1 = (const float*)d_in[4];
    const float* W2 = (const float*)d_in[5];
    const float* b2 = (const float*)d_in[6];
    const float* W3 = (const float*)d_in[7];
    const float* b3 = (const float*)d_in[8];
    float* out = (float*)d_out;

    const size_t smem_floats = (size_t)ROWS * LDA + 16 * HID + PRED * LDW3 +
                               25 * LDZ + 2 * HID + PRED + ROWS;
    const size_t smem_bytes = smem_floats * sizeof(float);
    cudaFuncSetAttribute(flow_kernel, cudaFuncAttributeMaxDynamicSharedMemorySize,
                         (int)smem_bytes);

    precompute_kernel<<<B_, HID>>>(past_target, W1, b1);
    flow_kernel<<<(S_ * B_) / ROWS, THREADS, smem_bytes>>>(z0, W1, W2, b2, W3, b3, out);
}